// round 3
// baseline (speedup 1.0000x reference)
#include <cuda_runtime.h>

#define S_LEN 2048
#define B_SZ 4
#define NHEAD 12
#define HDIM 64
#define HID 768
#define M_TOT (B_SZ * S_LEN)  // 8192

// Scratch: Q,K,V in [B, NH, S, HD] layout. 3 * 8192*768 floats = 75.5 MB static.
__device__ float g_qkv[3][(size_t)B_SZ * NHEAD * S_LEN * HDIM];

// ---------------------------------------------------------------------------
// Kernel 1: fused QKV projection.  out = X @ W{q,k,v} + b{q,k,v}
// Grid: (M/64, 3*768/64 = 36).  Block 256 threads, 64x64 tile, 4x4 micro-tile.
// Writes directly into [B,NH,S,HD] layout (tile N=64 == HD, so h is fixed per tile).
// ---------------------------------------------------------------------------
__global__ __launch_bounds__(256) void qkv_kernel(
    const float* __restrict__ X,
    const float* __restrict__ Wq, const float* __restrict__ bq,
    const float* __restrict__ Wk, const float* __restrict__ bk,
    const float* __restrict__ Wv, const float* __restrict__ bv)
{
    __shared__ float Xs[16 * 68];  // [k][m], padded stride 68
    __shared__ float Ws[16 * 68];  // [k][n], padded stride 68

    const int n0g = blockIdx.y * 64;        // 0..2303
    const int mat = n0g / HID;              // 0=Q, 1=K, 2=V
    const int c0  = n0g - mat * HID;        // col base within the 768 matrix

    const float* W;  const float* bias;
    if (mat == 0)      { W = Wq; bias = bq; }
    else if (mat == 1) { W = Wk; bias = bk; }
    else               { W = Wv; bias = bv; }

    const int m0  = blockIdx.x * 64;
    const int tid = threadIdx.x;
    const int ty  = tid >> 4, tx = tid & 15;

    // global-load roles
    const int xm = tid >> 2, xk4 = tid & 3;     // X: 64 rows x (4 threads * float4 = 16 k)
    const int wk = tid >> 4, wn4 = tid & 15;    // W: 16 k-rows x (16 threads * float4 = 64 n)

    const float* Xp = X + (size_t)(m0 + xm) * HID + xk4 * 4;
    const float* Wp = W + (size_t)wk * HID + c0 + wn4 * 4;

    float acc[4][4] = {};

    for (int k0 = 0; k0 < HID; k0 += 16) {
        float4 xv = *(const float4*)(Xp + k0);
        float4 wv = *(const float4*)(Wp + (size_t)k0 * HID);
        Xs[(xk4 * 4 + 0) * 68 + xm] = xv.x;
        Xs[(xk4 * 4 + 1) * 68 + xm] = xv.y;
        Xs[(xk4 * 4 + 2) * 68 + xm] = xv.z;
        Xs[(xk4 * 4 + 3) * 68 + xm] = xv.w;
        *(float4*)&Ws[wk * 68 + wn4 * 4] = wv;
        __syncthreads();

#pragma unroll
        for (int kk = 0; kk < 16; kk++) {
            float4 a = *(const float4*)&Xs[kk * 68 + ty * 4];
            float4 w = *(const float4*)&Ws[kk * 68 + tx * 4];
            acc[0][0] += a.x * w.x; acc[0][1] += a.x * w.y; acc[0][2] += a.x * w.z; acc[0][3] += a.x * w.w;
            acc[1][0] += a.y * w.x; acc[1][1] += a.y * w.y; acc[1][2] += a.y * w.z; acc[1][3] += a.y * w.w;
            acc[2][0] += a.z * w.x; acc[2][1] += a.z * w.y; acc[2][2] += a.z * w.z; acc[2][3] += a.z * w.w;
            acc[3][0] += a.w * w.x; acc[3][1] += a.w * w.y; acc[3][2] += a.w * w.z; acc[3][3] += a.w * w.w;
        }
        __syncthreads();
    }

    // epilogue: + bias, scatter into [B, NH, S, HD]
    float4 bb = *(const float4*)(bias + c0 + tx * 4);
    const int b      = m0 >> 11;                 // m0 / 2048 (64 | 2048, so constant per block)
    const int s_base = (m0 & (S_LEN - 1)) + ty * 4;
    const int h      = c0 >> 6;
    float* OUT = &g_qkv[mat][((size_t)(b * NHEAD + h) * S_LEN) * HDIM];

#pragma unroll
    for (int i = 0; i < 4; i++) {
        float4 o;
        o.x = acc[i][0] + bb.x; o.y = acc[i][1] + bb.y;
        o.z = acc[i][2] + bb.z; o.w = acc[i][3] + bb.w;
        *(float4*)&OUT[(size_t)(s_base + i) * HDIM + tx * 4] = o;
    }
}

// ---------------------------------------------------------------------------
// Kernel 2: flash attention (fp32, online softmax).
// Grid: (S/64 = 32, B*NH = 48). Block 256 threads.
// 64-query x 64-key tiles; HD = 64. O accumulator in registers (4x4/thread),
// P staged through smem for the PV product.
//   rows:  r = ty*4 + i    cols/d: c = tx + 16*j  (spread to dodge bank conflicts)
// ---------------------------------------------------------------------------
#define SMEM_ATTN_BYTES (4 * 64 * 68 * 4)  // Qs,Ks,Vs,Ps each 64x68 floats

__global__ __launch_bounds__(256) void attn_kernel(const float* __restrict__ mask,
                                                   float* __restrict__ out)
{
    extern __shared__ float sm[];
    float* Qs = sm;
    float* Ks = sm + 64 * 68;
    float* Vs = sm + 2 * 64 * 68;
    float* Ps = sm + 3 * 64 * 68;

    const int qt  = blockIdx.x;            // query tile
    const int bh  = blockIdx.y;            // b*NH + h
    const int b   = bh / NHEAD;
    const int h   = bh - b * NHEAD;
    const int tid = threadIdx.x;
    const int ty  = tid >> 4, tx = tid & 15;

    const float* Qg = g_qkv[0] + (size_t)bh * S_LEN * HDIM + (size_t)qt * 64 * HDIM;
    const float* Kg = g_qkv[1] + (size_t)bh * S_LEN * HDIM;
    const float* Vg = g_qkv[2] + (size_t)bh * S_LEN * HDIM;
    const float* mrow = mask + (size_t)b * S_LEN;

    // load Q tile (64x64) into padded smem
    for (int idx = tid; idx < 64 * 16; idx += 256) {
        int r = idx >> 4, d = (idx & 15) * 4;
        *(float4*)&Qs[r * 68 + d] = *(const float4*)(Qg + r * 64 + d);
    }

    float Oa[4][4] = {};
    float mr[4], lr[4];
#pragma unroll
    for (int i = 0; i < 4; i++) { mr[i] = -1e30f; lr[i] = 0.f; }

    for (int kt = 0; kt < S_LEN / 64; kt++) {
        __syncthreads();  // prior PV reads of Vs/Ps done; Q visible on first iter
        const float* Kt = Kg + (size_t)kt * 64 * HDIM;
        const float* Vt = Vg + (size_t)kt * 64 * HDIM;
        for (int idx = tid; idx < 64 * 16; idx += 256) {
            int r = idx >> 4, d = (idx & 15) * 4;
            *(float4*)&Ks[r * 68 + d] = *(const float4*)(Kt + r * 64 + d);
            *(float4*)&Vs[r * 68 + d] = *(const float4*)(Vt + r * 64 + d);
        }
        __syncthreads();

        // scores: S = Q K^T  (64x64 over d=64)
        float sc[4][4] = {};
#pragma unroll
        for (int d = 0; d < 64; d += 4) {
            float4 q[4], k[4];
#pragma unroll
            for (int i = 0; i < 4; i++) q[i] = *(const float4*)&Qs[(ty * 4 + i) * 68 + d];
#pragma unroll
            for (int j = 0; j < 4; j++) k[j] = *(const float4*)&Ks[(tx + 16 * j) * 68 + d];
#pragma unroll
            for (int i = 0; i < 4; i++)
#pragma unroll
                for (int j = 0; j < 4; j++)
                    sc[i][j] += q[i].x * k[j].x + q[i].y * k[j].y
                              + q[i].z * k[j].z + q[i].w * k[j].w;
        }

        float mv[4];
#pragma unroll
        for (int j = 0; j < 4; j++) mv[j] = __ldg(&mrow[kt * 64 + tx + 16 * j]);

        // online softmax per row
#pragma unroll
        for (int i = 0; i < 4; i++) {
            float tm = -1e30f;
#pragma unroll
            for (int j = 0; j < 4; j++) {
                sc[i][j] = sc[i][j] * 0.125f + mv[j];   // 1/sqrt(64) + mask
                tm = fmaxf(tm, sc[i][j]);
            }
            tm = fmaxf(tm, __shfl_xor_sync(0xffffffffu, tm, 1));
            tm = fmaxf(tm, __shfl_xor_sync(0xffffffffu, tm, 2));
            tm = fmaxf(tm, __shfl_xor_sync(0xffffffffu, tm, 4));
            tm = fmaxf(tm, __shfl_xor_sync(0xffffffffu, tm, 8));

            float mn   = fmaxf(mr[i], tm);
            float corr = __expf(mr[i] - mn);
            mr[i] = mn;

            float rs = 0.f;
#pragma unroll
            for (int j = 0; j < 4; j++) {
                float p = __expf(sc[i][j] - mn);
                sc[i][j] = p;
                rs += p;
            }
            rs += __shfl_xor_sync(0xffffffffu, rs, 1);
            rs += __shfl_xor_sync(0xffffffffu, rs, 2);
            rs += __shfl_xor_sync(0xffffffffu, rs, 4);
            rs += __shfl_xor_sync(0xffffffffu, rs, 8);
            lr[i] = lr[i] * corr + rs;

#pragma unroll
            for (int j = 0; j < 4; j++) Oa[i][j] *= corr;
#pragma unroll
            for (int j = 0; j < 4; j++) Ps[(ty * 4 + i) * 68 + tx + 16 * j] = sc[i][j];
        }
        __syncthreads();

        // O += P @ V   (P: 64x64 in smem, V tile: 64x64)
#pragma unroll 4
        for (int c = 0; c < 64; c += 4) {
            float4 p[4];
#pragma unroll
            for (int i = 0; i < 4; i++) p[i] = *(const float4*)&Ps[(ty * 4 + i) * 68 + c];
#pragma unroll
            for (int cc = 0; cc < 4; cc++) {
                float v0 = Vs[(c + cc) * 68 + tx];
                float v1 = Vs[(c + cc) * 68 + tx + 16];
                float v2 = Vs[(c + cc) * 68 + tx + 32];
                float v3 = Vs[(c + cc) * 68 + tx + 48];
#pragma unroll
                for (int i = 0; i < 4; i++) {
                    float pv = ((const float*)&p[i])[cc];
                    Oa[i][0] += pv * v0;
                    Oa[i][1] += pv * v1;
                    Oa[i][2] += pv * v2;
                    Oa[i][3] += pv * v3;
                }
            }
        }
    }

    // epilogue: O /= l, write [B,S,H] with h*HD offset
#pragma unroll
    for (int i = 0; i < 4; i++) {
        float inv = 1.0f / lr[i];
        int s = qt * 64 + ty * 4 + i;
        float* op = out + ((size_t)(b * S_LEN + s)) * HID + h * HDIM;
        op[tx]      = Oa[i][0] * inv;
        op[tx + 16] = Oa[i][1] * inv;
        op[tx + 32] = Oa[i][2] * inv;
        op[tx + 48] = Oa[i][3] * inv;
    }
}

// ---------------------------------------------------------------------------
extern "C" void kernel_launch(void* const* d_in, const int* in_sizes, int n_in,
                              void* d_out, int out_size)
{
    const float* X    = (const float*)d_in[0];  // hidden_states [4,2048,768]
    const float* mask = (const float*)d_in[1];  // attention_mask [4,1,1,2048]
    const float* Wq   = (const float*)d_in[2];
    const float* bq   = (const float*)d_in[3];
    const float* Wk   = (const float*)d_in[4];
    const float* bk   = (const float*)d_in[5];
    const float* Wv   = (const float*)d_in[6];
    const float* bv   = (const float*)d_in[7];
    float* out = (float*)d_out;                 // [4,2048,768]

    (void)in_sizes; (void)n_in; (void)out_size;

    cudaFuncSetAttribute(attn_kernel, cudaFuncAttributeMaxDynamicSharedMemorySize,
                         SMEM_ATTN_BYTES);

    dim3 g1(M_TOT / 64, (3 * HID) / 64);  // 128 x 36
    qkv_kernel<<<g1, 256>>>(X, Wq, bq, Wk, bk, Wv, bv);

    dim3 g2(S_LEN / 64, B_SZ * NHEAD);    // 32 x 48
    attn_kernel<<<g2, 256, SMEM_ATTN_BYTES>>>(mask, out);
}

// round 5
// speedup vs baseline: 3.0187x; 3.0187x over previous
#include <cuda_runtime.h>
#include <cstdint>

#define S_LEN 2048
#define B_SZ 4
#define NHEAD 12
#define HDIM 64
#define HID 768
#define M_TOT (B_SZ * S_LEN)  // 8192

// Scratch: Q,K,V in [B, NH, S, HD] layout + W^T for the GEMM B operand.
__device__ float g_qkv[3][(size_t)B_SZ * NHEAD * S_LEN * HDIM];
__device__ float g_wt[3][(size_t)HID * HID];  // [mat][n][k] = W[k][n]

// ---------------------------------------------------------------------------
// helpers: tf32 round + m16n8k8 mma (baseline PTX ISA — compiles at sm_103)
// ---------------------------------------------------------------------------
__device__ __forceinline__ float tf32r(float x) {
    uint32_t u;
    asm("cvt.rna.tf32.f32 %0, %1;" : "=r"(u) : "f"(x));
    return __uint_as_float(u);
}

__device__ __forceinline__ void mma8(float* c, const uint32_t* a, uint32_t b0, uint32_t b1) {
    asm volatile(
        "mma.sync.aligned.m16n8k8.row.col.f32.tf32.tf32.f32 "
        "{%0,%1,%2,%3}, {%4,%5,%6,%7}, {%8,%9}, {%0,%1,%2,%3};"
        : "+f"(c[0]), "+f"(c[1]), "+f"(c[2]), "+f"(c[3])
        : "r"(a[0]), "r"(a[1]), "r"(a[2]), "r"(a[3]), "r"(b0), "r"(b1));
}

// ---------------------------------------------------------------------------
// Kernel 0: transpose W -> g_wt[mat][n][k]
// ---------------------------------------------------------------------------
__global__ void wt_kernel(const float* __restrict__ Wq,
                          const float* __restrict__ Wk,
                          const float* __restrict__ Wv) {
    __shared__ float t[32][33];
    const float* W = blockIdx.z == 0 ? Wq : (blockIdx.z == 1 ? Wk : Wv);
    int k0 = blockIdx.x * 32, n0 = blockIdx.y * 32;
    int x = threadIdx.x, y = threadIdx.y;  // 32 x 8
#pragma unroll
    for (int i = 0; i < 32; i += 8) t[y + i][x] = W[(size_t)(k0 + y + i) * HID + n0 + x];
    __syncthreads();
    float* o = g_wt[blockIdx.z];
#pragma unroll
    for (int i = 0; i < 32; i += 8) o[(size_t)(n0 + y + i) * HID + k0 + x] = t[x][y + i];
}

// ---------------------------------------------------------------------------
// Kernel 1: QKV projection, mma.sync tf32.
// Block tile 128x128, K-tile 32, 8 warps (2m x 4n), warp tile 64x32.
// As[m][k] pad 36, Bs[n][k] pad 36 -> fragment LDS are bank-conflict-free:
//   bank = 4*(lane>>2) + (lane&3), a bijection onto 0..31.
// ---------------------------------------------------------------------------
#define GPAD 36

__global__ __launch_bounds__(256) void qkv_mma_kernel(
    const float* __restrict__ X,
    const float* __restrict__ bq, const float* __restrict__ bk,
    const float* __restrict__ bv)
{
    __shared__ float As[128 * GPAD];
    __shared__ float Bs[128 * GPAD];

    const int n0g = blockIdx.y * 128;
    const int mat = n0g / HID;
    const int c0  = n0g - mat * HID;
    const int m0  = blockIdx.x * 128;
    const float* bias = mat == 0 ? bq : (mat == 1 ? bk : bv);
    const float* Bsrc = g_wt[mat];

    const int tid = threadIdx.x, wid = tid >> 5, lane = tid & 31;
    const int warpM = wid >> 2, warpN = wid & 3;
    const int g = lane >> 2, tg = lane & 3;

    float c[4][4][4] = {};  // [mtile][ntile][frag]

    float4 av[4], bv4[4];
    {
        const float* Xb = X + (size_t)m0 * HID;
        const float* Bb = Bsrc + (size_t)c0 * HID;
#pragma unroll
        for (int i = 0; i < 4; i++) {
            int idx = tid + 256 * i, row = idx >> 3, kc = (idx & 7) * 4;
            av[i]  = *(const float4*)(Xb + (size_t)row * HID + kc);
            bv4[i] = *(const float4*)(Bb + (size_t)row * HID + kc);
        }
    }

    for (int t = 0; t < 24; t++) {
#pragma unroll
        for (int i = 0; i < 4; i++) {
            int idx = tid + 256 * i, row = idx >> 3, kc = (idx & 7) * 4;
            As[row * GPAD + kc + 0] = tf32r(av[i].x);
            As[row * GPAD + kc + 1] = tf32r(av[i].y);
            As[row * GPAD + kc + 2] = tf32r(av[i].z);
            As[row * GPAD + kc + 3] = tf32r(av[i].w);
            Bs[row * GPAD + kc + 0] = tf32r(bv4[i].x);
            Bs[row * GPAD + kc + 1] = tf32r(bv4[i].y);
            Bs[row * GPAD + kc + 2] = tf32r(bv4[i].z);
            Bs[row * GPAD + kc + 3] = tf32r(bv4[i].w);
        }
        __syncthreads();

        if (t < 23) {
            const float* Xb = X + (size_t)m0 * HID + (t + 1) * 32;
            const float* Bb = Bsrc + (size_t)c0 * HID + (t + 1) * 32;
#pragma unroll
            for (int i = 0; i < 4; i++) {
                int idx = tid + 256 * i, row = idx >> 3, kc = (idx & 7) * 4;
                av[i]  = *(const float4*)(Xb + (size_t)row * HID + kc);
                bv4[i] = *(const float4*)(Bb + (size_t)row * HID + kc);
            }
        }

#pragma unroll
        for (int ks = 0; ks < 4; ks++) {
            const int k0 = ks * 8;
            uint32_t a[4][4], b[4][2];
#pragma unroll
            for (int i = 0; i < 4; i++) {
                int r = warpM * 64 + i * 16;
                a[i][0] = __float_as_uint(As[(r + g) * GPAD + k0 + tg]);
                a[i][1] = __float_as_uint(As[(r + g + 8) * GPAD + k0 + tg]);
                a[i][2] = __float_as_uint(As[(r + g) * GPAD + k0 + tg + 4]);
                a[i][3] = __float_as_uint(As[(r + g + 8) * GPAD + k0 + tg + 4]);
            }
#pragma unroll
            for (int j = 0; j < 4; j++) {
                int n = warpN * 32 + j * 8;
                b[j][0] = __float_as_uint(Bs[(n + g) * GPAD + k0 + tg]);
                b[j][1] = __float_as_uint(Bs[(n + g) * GPAD + k0 + tg + 4]);
            }
#pragma unroll
            for (int i = 0; i < 4; i++)
#pragma unroll
                for (int j = 0; j < 4; j++) mma8(c[i][j], a[i], b[j][0], b[j][1]);
        }
        __syncthreads();
    }

    // epilogue: +bias, scatter to [B, NH, S, HD]
    const int bb_ = m0 >> 11, s0 = m0 & (S_LEN - 1);
#pragma unroll
    for (int j = 0; j < 4; j++) {
        int cn = warpN * 32 + j * 8 + tg * 2;
        int gc = c0 + cn;
        int h = gc >> 6, d = gc & 63;
        float2 bi = *(const float2*)(bias + gc);
        float* base = g_qkv[mat] + ((size_t)(bb_ * NHEAD + h) * S_LEN) * HDIM + d;
#pragma unroll
        for (int i = 0; i < 4; i++) {
            int r = warpM * 64 + i * 16 + g;
            float2 v0 = {c[i][j][0] + bi.x, c[i][j][1] + bi.y};
            float2 v1 = {c[i][j][2] + bi.x, c[i][j][3] + bi.y};
            *(float2*)(base + (size_t)(s0 + r) * HDIM)     = v0;
            *(float2*)(base + (size_t)(s0 + r + 8) * HDIM) = v1;
        }
    }
}

// ---------------------------------------------------------------------------
// Kernel 2: flash attention on mma.sync tf32.
// Grid (S/128 = 16, B*NH = 48), 256 threads = 8 warps; warp owns 16 q-rows.
// Per key tile (64 keys): S = Q K^T (Q frags in regs), warp-local online
// softmax, P restaged in per-warp smem, O += P V.
// Pads: Ks 68 (bank-free for B-frag), Vs 72 (bank-free transposed B-frag),
// Ps 68 (bank-free A-frag reload).
// ---------------------------------------------------------------------------
#define KPAD 68
#define VPAD 72
#define PPAD 68
#define ATTN_SMEM_BYTES ((2048 + 64 * KPAD + 64 * VPAD + 8 * 16 * PPAD) * 4)

__global__ __launch_bounds__(256) void attn_mma_kernel(const float* __restrict__ mask,
                                                       float* __restrict__ out)
{
    extern __shared__ float sm[];
    float* maskS = sm;
    float* Ks = sm + 2048;
    float* Vs = Ks + 64 * KPAD;
    float* Ps = Vs + 64 * VPAD;

    const int qt = blockIdx.x, bh = blockIdx.y;
    const int b = bh / NHEAD, h = bh - b * NHEAD;
    const int tid = threadIdx.x, wid = tid >> 5, lane = tid & 31;
    const int g = lane >> 2, tg = lane & 3;

    const float* Qg = g_qkv[0] + (size_t)bh * S_LEN * HDIM + (size_t)(qt * 128 + wid * 16) * HDIM;
    const float* Kg = g_qkv[1] + (size_t)bh * S_LEN * HDIM;
    const float* Vg = g_qkv[2] + (size_t)bh * S_LEN * HDIM;

    // mask row -> smem (once)
    for (int i = tid; i < 512; i += 256)
        *(float4*)(maskS + i * 4) = *(const float4*)(mask + (size_t)b * S_LEN + i * 4);

    // stage this warp's 16 Q rows, extract A-fragments (kept in regs all kernel)
    float* Pw = Ps + wid * 16 * PPAD;
    for (int i = lane; i < 256; i += 32) {  // 16 rows x 16 float4
        int r = i >> 4, d = (i & 15) * 4;
        float4 q = *(const float4*)(Qg + r * HDIM + d);
        Pw[r * PPAD + d + 0] = tf32r(q.x);
        Pw[r * PPAD + d + 1] = tf32r(q.y);
        Pw[r * PPAD + d + 2] = tf32r(q.z);
        Pw[r * PPAD + d + 3] = tf32r(q.w);
    }
    __syncwarp();
    uint32_t qa[8][4];
#pragma unroll
    for (int k = 0; k < 8; k++) {
        qa[k][0] = __float_as_uint(Pw[g * PPAD + k * 8 + tg]);
        qa[k][1] = __float_as_uint(Pw[(g + 8) * PPAD + k * 8 + tg]);
        qa[k][2] = __float_as_uint(Pw[g * PPAD + k * 8 + tg + 4]);
        qa[k][3] = __float_as_uint(Pw[(g + 8) * PPAD + k * 8 + tg + 4]);
    }

    float o[8][4] = {};
    float mrow[2] = {-1e30f, -1e30f}, lrow[2] = {0.f, 0.f};

    for (int kt = 0; kt < 32; kt++) {
        __syncthreads();  // all warps done with previous Ks/Vs (and mask load on iter 0)
        for (int i = tid; i < 1024; i += 256) {  // 64x64 tile, float4 per thread
            int r = i >> 4, d = (i & 15) * 4;
            float4 kv = *(const float4*)(Kg + (size_t)(kt * 64 + r) * HDIM + d);
            float4 vv = *(const float4*)(Vg + (size_t)(kt * 64 + r) * HDIM + d);
            Ks[r * KPAD + d + 0] = tf32r(kv.x);
            Ks[r * KPAD + d + 1] = tf32r(kv.y);
            Ks[r * KPAD + d + 2] = tf32r(kv.z);
            Ks[r * KPAD + d + 3] = tf32r(kv.w);
            Vs[r * VPAD + d + 0] = tf32r(vv.x);
            Vs[r * VPAD + d + 1] = tf32r(vv.y);
            Vs[r * VPAD + d + 2] = tf32r(vv.z);
            Vs[r * VPAD + d + 3] = tf32r(vv.w);
        }
        __syncthreads();

        // S = Q K^T : 16 x 64 per warp
        float sc[8][4] = {};
#pragma unroll
        for (int k = 0; k < 8; k++) {
#pragma unroll
            for (int j = 0; j < 8; j++) {
                uint32_t b0 = __float_as_uint(Ks[(j * 8 + g) * KPAD + k * 8 + tg]);
                uint32_t b1 = __float_as_uint(Ks[(j * 8 + g) * KPAD + k * 8 + tg + 4]);
                mma8(sc[j], qa[k], b0, b1);
            }
        }

        // scale + mask + warp-local online softmax (rows g and g+8)
        float mnew0 = mrow[0], mnew1 = mrow[1];
#pragma unroll
        for (int j = 0; j < 8; j++) {
            float2 mk = *(const float2*)(maskS + kt * 64 + j * 8 + tg * 2);
            sc[j][0] = sc[j][0] * 0.125f + mk.x;
            sc[j][1] = sc[j][1] * 0.125f + mk.y;
            sc[j][2] = sc[j][2] * 0.125f + mk.x;
            sc[j][3] = sc[j][3] * 0.125f + mk.y;
            mnew0 = fmaxf(mnew0, fmaxf(sc[j][0], sc[j][1]));
            mnew1 = fmaxf(mnew1, fmaxf(sc[j][2], sc[j][3]));
        }
        mnew0 = fmaxf(mnew0, __shfl_xor_sync(~0u, mnew0, 1));
        mnew0 = fmaxf(mnew0, __shfl_xor_sync(~0u, mnew0, 2));
        mnew1 = fmaxf(mnew1, __shfl_xor_sync(~0u, mnew1, 1));
        mnew1 = fmaxf(mnew1, __shfl_xor_sync(~0u, mnew1, 2));

        float corr0 = __expf(mrow[0] - mnew0);
        float corr1 = __expf(mrow[1] - mnew1);
        mrow[0] = mnew0; mrow[1] = mnew1;

        float rs0 = 0.f, rs1 = 0.f;
#pragma unroll
        for (int j = 0; j < 8; j++) {
            sc[j][0] = __expf(sc[j][0] - mnew0); rs0 += sc[j][0];
            sc[j][1] = __expf(sc[j][1] - mnew0); rs0 += sc[j][1];
            sc[j][2] = __expf(sc[j][2] - mnew1); rs1 += sc[j][2];
            sc[j][3] = __expf(sc[j][3] - mnew1); rs1 += sc[j][3];
        }
        rs0 += __shfl_xor_sync(~0u, rs0, 1);
        rs0 += __shfl_xor_sync(~0u, rs0, 2);
        rs1 += __shfl_xor_sync(~0u, rs1, 1);
        rs1 += __shfl_xor_sync(~0u, rs1, 2);
        lrow[0] = lrow[0] * corr0 + rs0;
        lrow[1] = lrow[1] * corr1 + rs1;

#pragma unroll
        for (int j = 0; j < 8; j++) {
            o[j][0] *= corr0; o[j][1] *= corr0;
            o[j][2] *= corr1; o[j][3] *= corr1;
        }

        // stage P (tf32) into per-warp smem
#pragma unroll
        for (int j = 0; j < 8; j++) {
            *(float2*)(Pw + g * PPAD + j * 8 + tg * 2) =
                make_float2(tf32r(sc[j][0]), tf32r(sc[j][1]));
            *(float2*)(Pw + (g + 8) * PPAD + j * 8 + tg * 2) =
                make_float2(tf32r(sc[j][2]), tf32r(sc[j][3]));
        }
        __syncwarp();

        // O += P V
#pragma unroll
        for (int k = 0; k < 8; k++) {
            uint32_t pa[4];
            pa[0] = __float_as_uint(Pw[g * PPAD + k * 8 + tg]);
            pa[1] = __float_as_uint(Pw[(g + 8) * PPAD + k * 8 + tg]);
            pa[2] = __float_as_uint(Pw[g * PPAD + k * 8 + tg + 4]);
            pa[3] = __float_as_uint(Pw[(g + 8) * PPAD + k * 8 + tg + 4]);
#pragma unroll
            for (int j = 0; j < 8; j++) {
                uint32_t b0 = __float_as_uint(Vs[(k * 8 + tg) * VPAD + j * 8 + g]);
                uint32_t b1 = __float_as_uint(Vs[(k * 8 + tg + 4) * VPAD + j * 8 + g]);
                mma8(o[j], pa, b0, b1);
            }
        }
    }

    // epilogue: O /= l, write [B,S,H]
    float inv0 = 1.f / lrow[0], inv1 = 1.f / lrow[1];
    int q0 = qt * 128 + wid * 16;
    float* ob = out + ((size_t)b * S_LEN) * HID + (size_t)h * HDIM;
#pragma unroll
    for (int j = 0; j < 8; j++) {
        int d = j * 8 + tg * 2;
        *(float2*)(ob + (size_t)(q0 + g) * HID + d) =
            make_float2(o[j][0] * inv0, o[j][1] * inv0);
        *(float2*)(ob + (size_t)(q0 + g + 8) * HID + d) =
            make_float2(o[j][2] * inv1, o[j][3] * inv1);
    }
}

// ---------------------------------------------------------------------------
extern "C" void kernel_launch(void* const* d_in, const int* in_sizes, int n_in,
                              void* d_out, int out_size)
{
    const float* X    = (const float*)d_in[0];
    const float* mask = (const float*)d_in[1];
    const float* Wq   = (const float*)d_in[2];
    const float* bq   = (const float*)d_in[3];
    const float* Wk   = (const float*)d_in[4];
    const float* bk   = (const float*)d_in[5];
    const float* Wv   = (const float*)d_in[6];
    const float* bv   = (const float*)d_in[7];
    float* out = (float*)d_out;

    (void)in_sizes; (void)n_in; (void)out_size;

    cudaFuncSetAttribute(attn_mma_kernel, cudaFuncAttributeMaxDynamicSharedMemorySize,
                         ATTN_SMEM_BYTES);

    dim3 gt(HID / 32, HID / 32, 3);
    wt_kernel<<<gt, dim3(32, 8)>>>(Wq, Wk, Wv);

    dim3 g1(M_TOT / 128, (3 * HID) / 128);  // 64 x 18
    qkv_mma_kernel<<<g1, 256>>>(X, bq, bk, bv);

    dim3 g2(S_LEN / 128, B_SZ * NHEAD);     // 16 x 48
    attn_mma_kernel<<<g2, 256, ATTN_SMEM_BYTES>>>(mask, out);
}